// round 16
// baseline (speedup 1.0000x reference)
#include <cuda_runtime.h>
#include <cstdint>

namespace {
constexpr int L2C   = 65536;
constexpr int NC    = 2 * L2C;      // 131072
constexpr int FINC  = 8;
constexpr int FOUTC = 8;
constexpr int KC    = 13;
constexpr int IK    = FINC * KC;    // 104
constexpr int EPB   = 32;           // edges per block
constexpr int TPB   = 256;          // 8 warps
constexpr int WPE   = IK * FOUTC;   // 832 mask elements per edge
constexpr int HWRD  = WPE / 2;      // 416 elements per (edge, o-half) warp task
}

// x transposed to (N, FIN): one gathered column = one 32B sector.
__device__ __align__(16) float g_xt[(size_t)NC * FINC];
// 0 => 4-byte mask words ({0,1} int32 or {0,1.0f} float32); 1 => 1-byte elements
__device__ int g_mask_is_byte;

__global__ __launch_bounds__(TPB) void prep_kernel(const float* __restrict__ x,
                                                   const uint32_t* __restrict__ M) {
    if (blockIdx.x == 0 && threadIdx.x < 32) {
        int bad = 0;
        #pragma unroll
        for (int r = 0; r < 8; r++) {
            uint32_t w = M[r * 32 + threadIdx.x];
            if (!(w == 0u || w == 1u || w == 0x3f800000u)) bad = 1;
        }
        bad = __any_sync(0xffffffffu, bad);
        if (threadIdx.x == 0) g_mask_is_byte = bad;
    }
    int j = blockIdx.x * blockDim.x + threadIdx.x;
    if (j >= NC) return;
    float4 a, b;
    a.x = x[0 * NC + j]; a.y = x[1 * NC + j]; a.z = x[2 * NC + j]; a.w = x[3 * NC + j];
    b.x = x[4 * NC + j]; b.y = x[5 * NC + j]; b.z = x[6 * NC + j]; b.w = x[7 * NC + j];
    float4* dst = reinterpret_cast<float4*>(g_xt) + (size_t)j * 2;
    dst[0] = a;
    dst[1] = b;
}

// ---- cache-policy load helpers ----
__device__ __forceinline__ uint64_t pol_evict_first() {
    uint64_t p;
    asm("createpolicy.fractional.L2::evict_first.b64 %0, 1.0;" : "=l"(p));
    return p;
}
__device__ __forceinline__ uint64_t pol_evict_last() {
    uint64_t p;
    asm("createpolicy.fractional.L2::evict_last.b64 %0, 1.0;" : "=l"(p));
    return p;
}
__device__ __forceinline__ uint32_t ld_stream_u32(const uint32_t* p, uint64_t pol) {
    uint32_t v;
    asm volatile("ld.global.nc.L2::cache_hint.u32 %0, [%1], %2;"
                 : "=r"(v) : "l"(p), "l"(pol));
    return v;
}
__device__ __forceinline__ uint32_t ld_stream_u8(const uint8_t* p, uint64_t pol) {
    uint32_t v;
    asm volatile("ld.global.nc.L2::cache_hint.u8 %0, [%1], %2;"
                 : "=r"(v) : "l"(p), "l"(pol));
    return v;
}
__device__ __forceinline__ float ld_pin_f32(const float* p, uint64_t pol) {
    float v;
    asm volatile("ld.global.nc.L2::cache_hint.f32 %0, [%1], %2;"
                 : "=f"(v) : "l"(p), "l"(pol));
    return v;
}
__device__ __forceinline__ int ld_pin_s32(const int* p, uint64_t pol) {
    int v;
    asm volatile("ld.global.nc.L2::cache_hint.s32 %0, [%1], %2;"
                 : "=r"(v) : "l"(p), "l"(pol));
    return v;
}

__global__ __launch_bounds__(TPB, 4) void edge_kernel(
    const float* __restrict__ Wh, const float* __restrict__ Wv,
    const float* __restrict__ bh, const float* __restrict__ bv,
    const uint8_t* __restrict__ Mh, const uint8_t* __restrict__ Mv,
    const int* __restrict__ Kh, const int* __restrict__ Kv,
    const int* __restrict__ ELh, const int* __restrict__ ELv,
    float* __restrict__ out)
{
    const bool vert = (blockIdx.y != 0);
    const float*   W    = vert ? Wv  : Wh;
    const float*   bias = vert ? bv  : bh;
    const uint8_t* M    = vert ? Mv  : Mh;
    const int*     KER  = vert ? Kv  : Kh;
    const int*     EL   = vert ? ELv : ELh;

    const int tid  = threadIdx.x;
    const int lane = tid & 31;
    const int w    = tid >> 5;          // warp 0..7
    const int e0   = blockIdx.x * EPB;

    const uint64_t polF = pol_evict_first();   // mask stream
    const uint64_t polL = pol_evict_last();    // g_xt / ker: pin in L2

    // ---- warp roles: h = o-half, eo = edge slot; lane = o_local*8 + ii ----
    const int h  = w >> 2;
    const int eo = w & 3;
    const int ii = lane & 7;
    const int o  = h * 4 + (lane >> 3);
    const int lp = h * 32 + lane;       // o*8 + ii

    // W row (o, ii): 13 registers; bias in register
    float wreg[KC];
    #pragma unroll
    for (int k = 0; k < KC; k++) wreg[k] = __ldg(&W[lp * KC + k]);
    const float bo = __ldg(&bias[o]);

    const int isbyte = g_mask_is_byte;
    const uint32_t* Mw = reinterpret_cast<const uint32_t*>(M);
    const uint8_t*  M8 = M;

    const float SCALE = (float)((2.0 + 2.0 * 2.718281828459045235) /
                                (2.718281828459045235 - 1.0));

    // this lane's bit window inside the 416-bit half-row
    const int bitpos = lane * KC;            // 13*lane
    const int it0    = bitpos >> 5;
    const int sh     = bitpos & 31;

    #pragma unroll 1
    for (int t = 0; t < 8; t++) {
        const int e  = eo + 4 * t;                    // block-local edge
        const int ge = e0 + e;                        // global edge
        const size_t mb = (size_t)ge * WPE + (size_t)h * HWRD;  // element offset

        // ---- 13 coalesced streaming mask loads (independent -> full MLP) ----
        uint32_t pw[KC];
        if (!isbyte) {
            #pragma unroll
            for (int it = 0; it < KC; it++)
                pw[it] = ld_stream_u32(Mw + mb + it * 32 + lane, polF);
        } else {
            #pragma unroll
            for (int it = 0; it < KC; it++)
                pw[it] = ld_stream_u8(M8 + mb + it * 32 + lane, polF);
        }

        // ---- ker row (broadcast, L2-pinned) then x sectors (L2-pinned) ----
        int jv[KC];
        #pragma unroll
        for (int k = 0; k < KC; k++) jv[k] = ld_pin_s32(&KER[ge * KC + k], polL);
        float xv[KC];
        #pragma unroll
        for (int k = 0; k < KC; k++)
            xv[k] = ld_pin_f32(&g_xt[(size_t)jv[k] * FINC + ii], polL);

        // ---- words -> bits via ballot; lane keeps its 2 covering words ----
        uint32_t r0 = 0, r1 = 0;
        #pragma unroll
        for (int it = 0; it < KC; it++) {
            uint32_t bm = __ballot_sync(0xffffffffu, pw[it] != 0u);
            if (it == it0)     r0 = bm;
            if (it == it0 + 1) r1 = bm;
        }
        const uint32_t m = __funnelshift_r(r0, r1, sh);

        // ---- 13 masked MACs ----
        float acc = 0.0f;
        #pragma unroll
        for (int k = 0; k < KC; k++)
            if (m & (1u << k)) acc = fmaf(wreg[k], xv[k], acc);

        // reduce over input features (lane bits 0..2)
        acc += __shfl_xor_sync(0xffffffffu, acc, 1);
        acc += __shfl_xor_sync(0xffffffffu, acc, 2);
        acc += __shfl_xor_sync(0xffffffffu, acc, 4);

        if (ii == 0) {
            float z = acc + bo;
            float s = 1.0f / (1.0f + __expf(-z));
            __stcs(&out[(size_t)o * NC + __ldg(&EL[ge])], (s - 0.5f) * SCALE);
        }
    }
}

extern "C" void kernel_launch(void* const* d_in, const int* in_sizes, int n_in,
                              void* d_out, int out_size) {
    const float*   x   = (const float*)  d_in[0];
    const float*   Wh  = (const float*)  d_in[1];
    const float*   Wv  = (const float*)  d_in[2];
    const float*   bh  = (const float*)  d_in[3];
    const float*   bv  = (const float*)  d_in[4];
    const uint8_t* Mh  = (const uint8_t*)d_in[5];
    const uint8_t* Mv  = (const uint8_t*)d_in[6];
    const int*     Kh  = (const int*)    d_in[7];
    const int*     Kv  = (const int*)    d_in[8];
    const int*     ELh = (const int*)    d_in[9];
    const int*     ELv = (const int*)    d_in[10];
    float* out = (float*)d_out;

    prep_kernel<<<NC / TPB, TPB>>>(x, (const uint32_t*)Mh);

    dim3 grid(L2C / EPB, 2);   // y=0 horizontal branch, y=1 vertical
    edge_kernel<<<grid, TPB>>>(Wh, Wv, bh, bv, Mh, Mv, Kh, Kv, ELh, ELv, out);
}

// round 17
// speedup vs baseline: 1.1740x; 1.1740x over previous
#include <cuda_runtime.h>
#include <cstdint>

namespace {
constexpr int L2C   = 65536;
constexpr int NC    = 2 * L2C;      // 131072
constexpr int FINC  = 8;
constexpr int FOUTC = 8;
constexpr int KC    = 13;
constexpr int IK    = FINC * KC;    // 104
constexpr int EPB   = 32;           // edges per block
constexpr int TPB   = 256;
constexpr int CHE   = 8;            // edges per chunk (doubled vs R14)
constexpr int NCH   = EPB / CHE;    // 4 chunks
constexpr int WPE   = IK * FOUTC;   // 832 mask elements per edge
constexpr int CHWRD = CHE * WPE;    // 6656 elements per chunk
constexpr int CHB_W = CHWRD * 4;    // 26624 B per chunk (word masks)
constexpr int RING_B= 2 * CHB_W;    // 53248 B dynamic smem ring
}

// x transposed to (N, FIN): one gathered column = one 32B sector.
__device__ __align__(16) float g_xt[(size_t)NC * FINC];
// 0 => 4-byte mask words ({0,1} int32 or {0,1.0f} float32); 1 => 1-byte elements
__device__ int g_mask_is_byte;

__global__ __launch_bounds__(TPB) void prep_kernel(const float* __restrict__ x,
                                                   const uint32_t* __restrict__ M) {
    if (blockIdx.x == 0 && threadIdx.x < 32) {
        int bad = 0;
        #pragma unroll
        for (int r = 0; r < 8; r++) {
            uint32_t w = M[r * 32 + threadIdx.x];
            if (!(w == 0u || w == 1u || w == 0x3f800000u)) bad = 1;
        }
        bad = __any_sync(0xffffffffu, bad);
        if (threadIdx.x == 0) g_mask_is_byte = bad;
    }
    int j = blockIdx.x * blockDim.x + threadIdx.x;
    if (j >= NC) return;
    float4 a, b;
    a.x = x[0 * NC + j]; a.y = x[1 * NC + j]; a.z = x[2 * NC + j]; a.w = x[3 * NC + j];
    b.x = x[4 * NC + j]; b.y = x[5 * NC + j]; b.z = x[6 * NC + j]; b.w = x[7 * NC + j];
    float4* dst = reinterpret_cast<float4*>(g_xt) + (size_t)j * 2;
    dst[0] = a;
    dst[1] = b;
}

// ---- cache-policy + cp.async helpers ----
__device__ __forceinline__ uint64_t pol_evict_first() {
    uint64_t p;
    asm("createpolicy.fractional.L2::evict_first.b64 %0, 1.0;" : "=l"(p));
    return p;
}
__device__ __forceinline__ uint64_t pol_evict_last() {
    uint64_t p;
    asm("createpolicy.fractional.L2::evict_last.b64 %0, 1.0;" : "=l"(p));
    return p;
}
__device__ __forceinline__ void cp16_stream(uint32_t dst_smem, const void* src, uint64_t pol) {
    asm volatile("cp.async.cg.shared.global.L2::cache_hint [%0], [%1], 16, %2;"
                 :: "r"(dst_smem), "l"(src), "l"(pol) : "memory");
}
__device__ __forceinline__ void cp_commit() {
    asm volatile("cp.async.commit_group;" ::: "memory");
}
template <int N> __device__ __forceinline__ void cp_wait() {
    asm volatile("cp.async.wait_group %0;" :: "n"(N) : "memory");
}
__device__ __forceinline__ float ld_pin(const float* p, uint64_t pol) {
    float v;
    asm volatile("ld.global.nc.L2::cache_hint.f32 %0, [%1], %2;"
                 : "=f"(v) : "l"(p), "l"(pol));
    return v;
}

__global__ __launch_bounds__(TPB, 3) void edge_kernel(
    const float* __restrict__ Wh, const float* __restrict__ Wv,
    const float* __restrict__ bh, const float* __restrict__ bv,
    const uint8_t* __restrict__ Mh, const uint8_t* __restrict__ Mv,
    const int* __restrict__ Kh, const int* __restrict__ Kv,
    const int* __restrict__ ELh, const int* __restrict__ ELv,
    float* __restrict__ out)
{
    extern __shared__ __align__(128) uint32_t mbuf[];   // 2 x CHWRD words (ring)

    const bool vert = (blockIdx.y != 0);
    const float*   W    = vert ? Wv  : Wh;
    const float*   bias = vert ? bv  : bh;
    const uint8_t* M    = vert ? Mv  : Mh;
    const int*     KER  = vert ? Kv  : Kh;
    const int*     EL   = vert ? ELv : ELh;

    __shared__ __align__(16) float    xsf[EPB * IK];       // 13312 B
    __shared__ int   kers[EPB * KC];
    __shared__ int   els[EPB];
    __shared__ float bsh[FOUTC];

    const int tid = threadIdx.x;
    const int e0  = blockIdx.x * EPB;

    const uint64_t polF = pol_evict_first();   // mask stream: don't occupy L2
    const uint64_t polL = pol_evict_last();    // g_xt: pin in L2

    // ---- small tables ----
    for (int t = tid; t < EPB * KC; t += TPB) kers[t] = KER[e0 * KC + t];
    if (tid < EPB)   els[tid] = EL[e0 + tid];
    if (tid < FOUTC) bsh[tid] = bias[tid];

    // ---- roles: tid = celA<2b> | lp<6b>; thread handles edges celA and celA+4 ----
    const int celA = tid >> 6;           // 0..3
    const int celB = celA + 4;           // 4..7
    const int lp   = tid & 63;
    const int o    = lp >> 3;
    const int ii   = lp & 7;

    // W row (o, ii): 13 registers (L2-resident)
    float wreg[KC];
    #pragma unroll
    for (int k = 0; k < KC; k++) wreg[k] = __ldg(&W[lp * KC + k]);

    const int isbyte = g_mask_is_byte;
    const int esz    = isbyte ? 1 : 4;
    const int chb    = CHWRD * esz;                 // bytes per chunk
    const int nops   = chb >> 4;                    // 16B cp.async ops per chunk
    const uint8_t* Mbase = M + (size_t)e0 * WPE * esz;
    const uint32_t mb_s  = (uint32_t)__cvta_generic_to_shared(mbuf);

    // ---- prologue: chunks 0 AND 1 in flight before the x gather ----
    for (int u = tid; u < nops; u += TPB)
        cp16_stream(mb_s + u * 16, Mbase + (size_t)u * 16, polF);
    cp_commit();                                    // group: chunk 0
    for (int u = tid; u < nops; u += TPB)
        cp16_stream(mb_s + CHB_W + u * 16, Mbase + (size_t)chb + (size_t)u * 16, polF);
    cp_commit();                                    // group: chunk 1

    __syncthreads();   // kers visible for gather

    // ---- gather x once per block (L2-pinned loads) ----
    {
        const int gel = tid >> 3, gi = tid & 7;
        #pragma unroll
        for (int k = 0; k < KC; k++) {
            int j = kers[gel * KC + k];
            xsf[gel * IK + gi * KC + k] = ld_pin(&g_xt[(size_t)j * FINC + gi], polL);
        }
    }

    const float SCALE = (float)((2.0 + 2.0 * 2.718281828459045235) /
                                (2.718281828459045235 - 1.0));

    #pragma unroll 1
    for (int c = 0; c < NCH; c++) {
        const int bsel = c & 1;

        // ---- issue chunk c+1 into the other buffer (chunks 0,1 pre-issued) ----
        if (c >= 1 && c + 1 < NCH) {
            const uint8_t* src = Mbase + (size_t)(c + 1) * chb;
            const uint32_t dst = mb_s + (bsel ^ 1) * CHB_W;
            for (int u = tid; u < nops; u += TPB)
                cp16_stream(dst + u * 16, src + (size_t)u * 16, polF);
            cp_commit();
        }
        if (c + 1 < NCH) cp_wait<1>();   // chunk c landed
        else             cp_wait<0>();
        __syncthreads();                 // publish chunk c; xsf ready (c==0)

        // ---- compute chunk c: thread (celA/B, o, ii) does 2 x 13 MACs ----
        const int egA = c * CHE + celA;
        const int egB = c * CHE + celB;
        const float* xrowA = &xsf[egA * IK + ii * KC];
        const float* xrowB = &xsf[egB * IK + ii * KC];

        float accA = 0.0f, accB = 0.0f;
        if (!isbyte) {
            const uint32_t* mrowA = mbuf + bsel * CHWRD + celA * WPE + lp * KC;
            const uint32_t* mrowB = mbuf + bsel * CHWRD + celB * WPE + lp * KC;
            #pragma unroll
            for (int k = 0; k < KC; k++) {
                if (mrowA[k]) accA = fmaf(wreg[k], xrowA[k], accA);
                if (mrowB[k]) accB = fmaf(wreg[k], xrowB[k], accB);
            }
        } else {
            const uint8_t* mrowA = reinterpret_cast<const uint8_t*>(mbuf) +
                                   bsel * CHB_W + celA * WPE + lp * KC;
            const uint8_t* mrowB = reinterpret_cast<const uint8_t*>(mbuf) +
                                   bsel * CHB_W + celB * WPE + lp * KC;
            #pragma unroll
            for (int k = 0; k < KC; k++) {
                if (mrowA[k]) accA = fmaf(wreg[k], xrowA[k], accA);
                if (mrowB[k]) accB = fmaf(wreg[k], xrowB[k], accB);
            }
        }

        // reduce over input features (lane bits 0..2) — two independent trees
        accA += __shfl_xor_sync(0xffffffffu, accA, 1);
        accB += __shfl_xor_sync(0xffffffffu, accB, 1);
        accA += __shfl_xor_sync(0xffffffffu, accA, 2);
        accB += __shfl_xor_sync(0xffffffffu, accB, 2);
        accA += __shfl_xor_sync(0xffffffffu, accA, 4);
        accB += __shfl_xor_sync(0xffffffffu, accB, 4);

        if (ii == 0) {
            float zA = accA + bsh[o];
            float zB = accB + bsh[o];
            float sA = 1.0f / (1.0f + __expf(-zA));
            float sB = 1.0f / (1.0f + __expf(-zB));
            __stcs(&out[(size_t)o * NC + els[egA]], (sA - 0.5f) * SCALE);
            __stcs(&out[(size_t)o * NC + els[egB]], (sB - 0.5f) * SCALE);
        }
        __syncthreads();   // buffer bsel free for reuse next iteration
    }
}

extern "C" void kernel_launch(void* const* d_in, const int* in_sizes, int n_in,
                              void* d_out, int out_size) {
    const float*   x   = (const float*)  d_in[0];
    const float*   Wh  = (const float*)  d_in[1];
    const float*   Wv  = (const float*)  d_in[2];
    const float*   bh  = (const float*)  d_in[3];
    const float*   bv  = (const float*)  d_in[4];
    const uint8_t* Mh  = (const uint8_t*)d_in[5];
    const uint8_t* Mv  = (const uint8_t*)d_in[6];
    const int*     Kh  = (const int*)    d_in[7];
    const int*     Kv  = (const int*)    d_in[8];
    const int*     ELh = (const int*)    d_in[9];
    const int*     ELv = (const int*)    d_in[10];
    float* out = (float*)d_out;

    cudaFuncSetAttribute(edge_kernel,
                         cudaFuncAttributeMaxDynamicSharedMemorySize, RING_B);

    prep_kernel<<<NC / TPB, TPB>>>(x, (const uint32_t*)Mh);

    dim3 grid(L2C / EPB, 2);   // y=0 horizontal branch, y=1 vertical
    edge_kernel<<<grid, TPB, RING_B>>>(Wh, Wv, bh, bv, Mh, Mv, Kh, Kv, ELh, ELv, out);
}